// round 1
// baseline (speedup 1.0000x reference)
#include <cuda_runtime.h>
#include <cuda_bf16.h>

#define RESO   128
#define NRAYS  16384
#define NSAMP  192

// Warp-per-ray volume renderer.
// lane c in [0,27): owns SH channel c (sh layout [x][y][z][27] -> coalesced).
// All lanes redundantly compute positions/weights/sigma (uniform -> uniform branches).
// Corner values cached in registers across samples that stay in the same cell.
__global__ __launch_bounds__(256, 8) void render_kernel(
    const float* __restrict__ origins,
    const float* __restrict__ dirs,
    const float* __restrict__ density,
    const float* __restrict__ sh,
    float* __restrict__ out)
{
    const unsigned FULL = 0xffffffffu;
    int ray  = (blockIdx.x * blockDim.x + threadIdx.x) >> 5;
    int lane = threadIdx.x & 31;
    if (ray >= NRAYS) return;

    float ox = origins[3*ray+0], oy = origins[3*ray+1], oz = origins[3*ray+2];
    float dx = dirs[3*ray+0],    dy = dirs[3*ray+1],    dz = dirs[3*ray+2];

    // Per-lane SH basis coefficient (svox2 convention), lane c -> basis[c % 9].
    float bl = 0.0f;
    {
        const float C0 = 0.28209479177387814f;
        const float C1 = 0.4886025119029199f;
        float b[9];
        b[0] = C0;
        b[1] = -C1 * dy;
        b[2] =  C1 * dz;
        b[3] = -C1 * dx;
        b[4] =  1.0925484305920792f * dx * dy;
        b[5] = -1.0925484305920792f * dy * dz;
        b[6] =  0.31539156525252005f * (2.0f*dz*dz - dx*dx - dy*dy);
        b[7] = -1.0925484305920792f * dx * dz;
        b[8] =  0.5462742152960396f * (dx*dx - dy*dy);
        if (lane < 27) bl = b[lane % 9];
    }

    float accum = 0.0f;   // color partial sums live at lanes 0, 9, 18
    float T     = 1.0f;   // transmittance
    int   prev_cell = -1;
    float shc[8];         // cached SH corner values for this lane's channel
    float dn[8];          // cached density corner values (same in every lane)

    #pragma unroll 1
    for (int s = 0; s < NSAMP; ++s) {
        float t  = ((float)s + 0.5f) * 0.5f;
        float px = fmaf(t, dx, ox);
        float py = fmaf(t, dy, oy);
        float pz = fmaf(t, dz, oz);

        // Straight ray from an interior origin: in-bounds set is a t-interval,
        // and the reference zeroes all out-of-bounds contributions -> exact break.
        if (!(px >= 0.0f && px <= 127.0f &&
              py >= 0.0f && py <= 127.0f &&
              pz >= 0.0f && pz <= 127.0f)) break;

        float fx = floorf(px), fy = floorf(py), fz = floorf(pz);
        int ix = min((int)fx, RESO - 2);
        int iy = min((int)fy, RESO - 2);
        int iz = min((int)fz, RESO - 2);
        float ax = px - fx, ay = py - fy, az = pz - fz;

        int cell = (ix * RESO + iy) * RESO + iz;
        if (cell != prev_cell) {            // warp-uniform
            prev_cell = cell;
            #pragma unroll
            for (int j = 0; j < 8; ++j) {
                // j bits: [2]=dx [1]=dy [0]=dz -> matches reference corner order
                int ci = cell + ((j >> 2) & 1) * (RESO * RESO)
                              + ((j >> 1) & 1) * RESO
                              + (j & 1);
                dn[j] = __ldg(density + ci);
                if (lane < 27) shc[j] = __ldg(sh + ci * 27 + lane);
            }
        }

        float wx0 = 1.0f - ax, wx1 = ax;
        float wy0 = 1.0f - ay, wy1 = ay;
        float wz0 = 1.0f - az, wz1 = az;
        float w[8] = { wx0*wy0*wz0, wx0*wy0*wz1, wx0*wy1*wz0, wx0*wy1*wz1,
                       wx1*wy0*wz0, wx1*wy0*wz1, wx1*wy1*wz0, wx1*wy1*wz1 };

        float sigma = 0.0f, shv = 0.0f;
        #pragma unroll
        for (int j = 0; j < 8; ++j) {
            sigma = fmaf(w[j], dn[j],  sigma);
            shv   = fmaf(w[j], shc[j], shv);
        }

        if (sigma > 1e-10f) {               // warp-uniform (sigma identical in all lanes)
            float att = __expf(-0.5f * sigma);
            float wgt = T * (1.0f - att);
            T *= att;

            // Reduce shv*basis over lane groups {0..8},{9..17},{18..26}.
            float p = (lane < 27) ? shv * bl : 0.0f;
            float v = p;
            v += __shfl_down_sync(FULL, v, 1);
            v += __shfl_down_sync(FULL, v, 2);
            v += __shfl_down_sync(FULL, v, 4);          // lane b: sum p[b..b+7]
            v += __shfl_sync(FULL, p, (lane + 8) & 31); // + p[b+8]
            float rgb = fmaxf(v + 0.5f, 0.0f);
            if (lane == 0 || lane == 9 || lane == 18)
                accum = fmaf(wgt, rgb, accum);
        }
    }

    // Gather the three color channels to lane 0 and add empty-space term.
    float r1 = __shfl_sync(FULL, accum, 9);
    float r2 = __shfl_sync(FULL, accum, 18);
    if (lane == 0) {
        out[3*ray+0] = accum + T;
        out[3*ray+1] = r1    + T;
        out[3*ray+2] = r2    + T;
    }
}

extern "C" void kernel_launch(void* const* d_in, const int* in_sizes, int n_in,
                              void* d_out, int out_size)
{
    const float* origins = (const float*)d_in[0];
    const float* dirs    = (const float*)d_in[1];
    const float* density = (const float*)d_in[2];
    const float* sh      = (const float*)d_in[3];
    float* out = (float*)d_out;

    // 8 warps (8 rays) per block, 2048 blocks -> 16384 rays
    render_kernel<<<NRAYS / 8, 256>>>(origins, dirs, density, sh, out);
}